// round 1
// baseline (speedup 1.0000x reference)
#include <cuda_runtime.h>
#include <math_constants.h>

// CrossMHA: B=2, S=2048, DIM=1024, H=16, DK=64, heads-last layout [b,s,dk,h]
namespace {
constexpr int B_ = 2, S_ = 2048, DIM_ = 1024, H_ = 16, DK_ = 64;
constexpr float NEGV = -10000000000.0f;
}

// Scratch (static device globals; no allocation in kernel_launch)
__device__ float g_Q[B_ * S_ * DIM_];        // dec @ Wq^T, [b,s,dim]
__device__ float g_KV[B_ * S_ * 2 * DIM_];   // enc @ Wkv^T, [b,s,2*dim]
__device__ float g_Qh[B_ * S_ * DIM_];       // [b,h,s,dk]
__device__ float g_Kh[B_ * S_ * DIM_];
__device__ float g_Vh[B_ * S_ * DIM_];
__device__ float g_Oh[B_ * S_ * DIM_];       // attention out, [b,h,s,dk]
__device__ float g_attn[B_ * S_ * DIM_];     // repacked to [b,s,dim] heads-last

// ---------------------------------------------------------------------------
// GEMM: C[M,N] = A[M,K] * W[N,K]^T   (fp32, 128x128x16 tile, 8x8 per thread)
// ---------------------------------------------------------------------------
__global__ __launch_bounds__(256, 2)
void gemm_nt(const float* __restrict__ A, const float* __restrict__ W,
             float* __restrict__ C, int M, int N, int K) {
  __shared__ float As[16][128];
  __shared__ float Bs[16][128];
  const int bm = blockIdx.y * 128;
  const int bn = blockIdx.x * 128;
  const int tid = threadIdx.x;
  const int tx = tid & 15, ty = tid >> 4;

  float acc[8][8];
#pragma unroll
  for (int i = 0; i < 8; i++)
#pragma unroll
    for (int j = 0; j < 8; j++) acc[i][j] = 0.f;

  for (int k0 = 0; k0 < K; k0 += 16) {
#pragma unroll
    for (int l = 0; l < 2; l++) {
      int idx = tid + l * 256;
      int r = idx >> 2;             // 0..127
      int c = (idx & 3) << 2;       // 0,4,8,12
      float4 va = *(const float4*)(A + (size_t)(bm + r) * K + k0 + c);
      As[c + 0][r] = va.x; As[c + 1][r] = va.y;
      As[c + 2][r] = va.z; As[c + 3][r] = va.w;
      float4 vb = *(const float4*)(W + (size_t)(bn + r) * K + k0 + c);
      Bs[c + 0][r] = vb.x; Bs[c + 1][r] = vb.y;
      Bs[c + 2][r] = vb.z; Bs[c + 3][r] = vb.w;
    }
    __syncthreads();
#pragma unroll
    for (int kk = 0; kk < 16; kk++) {
      float a[8], b[8];
      *(float4*)(a)     = *(const float4*)&As[kk][ty * 8];
      *(float4*)(a + 4) = *(const float4*)&As[kk][ty * 8 + 4];
      *(float4*)(b)     = *(const float4*)&Bs[kk][tx * 8];
      *(float4*)(b + 4) = *(const float4*)&Bs[kk][tx * 8 + 4];
#pragma unroll
      for (int i = 0; i < 8; i++)
#pragma unroll
        for (int j = 0; j < 8; j++) acc[i][j] += a[i] * b[j];
    }
    __syncthreads();
  }

#pragma unroll
  for (int i = 0; i < 8; i++) {
    float* cp = C + (size_t)(bm + ty * 8 + i) * N + bn + tx * 8;
    *(float4*)cp       = make_float4(acc[i][0], acc[i][1], acc[i][2], acc[i][3]);
    *(float4*)(cp + 4) = make_float4(acc[i][4], acc[i][5], acc[i][6], acc[i][7]);
  }
}

// ---------------------------------------------------------------------------
// Repack: [b,s, d*16+h] -> [b,h,s,d] for Q, K, V. One block per (b,s) row.
// Pad-swizzled smem staging keeps both gmem sides coalesced, no bank conflicts.
// ---------------------------------------------------------------------------
__global__ void repack_qkv() {
  __shared__ float bq[1056], bk[1056], bv[1056];  // 1024 + 32 pad slots
  const int bs = blockIdx.x;
  const int b = bs >> 11;          // /S_
  const int s = bs & (S_ - 1);
  const int tid = threadIdx.x;
  const float* qrow  = g_Q  + (size_t)bs * DIM_;
  const float* kvrow = g_KV + (size_t)bs * 2 * DIM_;
#pragma unroll
  for (int l = 0; l < 4; l++) {
    int i = tid + l * 256;
    bq[i + (i >> 5)] = qrow[i];
    bk[i + (i >> 5)] = kvrow[i];
    bv[i + (i >> 5)] = kvrow[DIM_ + i];
  }
  __syncthreads();
#pragma unroll
  for (int l = 0; l < 4; l++) {
    int idx = tid + l * 256;
    int h = idx >> 6, d = idx & 63;
    int a = d * H_ + h;
    a += a >> 5;
    size_t o = ((size_t)(b * H_ + h) * S_ + s) * DK_ + d;
    g_Qh[o] = bq[a];
    g_Kh[o] = bk[a];
    g_Vh[o] = bv[a];
  }
}

// ---------------------------------------------------------------------------
// Unpack: [b,h,s,d] -> [b,s, d*16+h]
// ---------------------------------------------------------------------------
__global__ void unpack_o() {
  __shared__ float buf[1056];
  const int bs = blockIdx.x;
  const int b = bs >> 11;
  const int s = bs & (S_ - 1);
  const int tid = threadIdx.x;
#pragma unroll
  for (int l = 0; l < 4; l++) {
    int idx = tid + l * 256;
    int h = idx >> 6, d = idx & 63;
    int a = d * H_ + h;
    buf[a + (a >> 5)] = g_Oh[((size_t)(b * H_ + h) * S_ + s) * DK_ + d];
  }
  __syncthreads();
#pragma unroll
  for (int l = 0; l < 4; l++) {
    int i = tid + l * 256;
    g_attn[(size_t)bs * DIM_ + i] = buf[i + (i >> 5)];
  }
}

// ---------------------------------------------------------------------------
// Flash attention per (b, h, 64-query tile). 64x64 key tiles, 4x4 per thread.
// K tile XOR-skewed in smem; P tile reuses K buffer (48 KB static smem total).
// ---------------------------------------------------------------------------
__global__ __launch_bounds__(256, 2)
void attn_kernel(const int* __restrict__ mask) {
  __shared__ float Qs[64 * 64];
  __shared__ float KPs[64 * 64];   // K (skewed), later P (plain)
  __shared__ float Vs[64 * 64];

  const int qt = blockIdx.x, h = blockIdx.y, b = blockIdx.z;
  const int tid = threadIdx.x, tx = tid & 15, ty = tid >> 4;
  const float* Qp = g_Qh + ((size_t)(b * H_ + h) * S_ + qt * 64) * DK_;
  const float* Kp = g_Kh + (size_t)(b * H_ + h) * S_ * DK_;
  const float* Vp = g_Vh + (size_t)(b * H_ + h) * S_ * DK_;
  const int*   Mp = mask + ((size_t)b * S_ + qt * 64) * S_;

#pragma unroll
  for (int l = 0; l < 4; l++) {
    int idx = tid + l * 256;
    int r = idx >> 4, c = (idx & 15) << 2;
    *(float4*)&Qs[r * 64 + c] = *(const float4*)(Qp + r * DK_ + c);
  }

  float m[4], lsum[4], acc[4][4];
#pragma unroll
  for (int i = 0; i < 4; i++) {
    m[i] = -CUDART_INF_F;
    lsum[i] = 0.f;
#pragma unroll
    for (int j = 0; j < 4; j++) acc[i][j] = 0.f;
  }

  for (int k0 = 0; k0 < S_; k0 += 64) {
    __syncthreads();  // Qs ready (iter 0) / previous P,V fully consumed
#pragma unroll
    for (int l = 0; l < 4; l++) {
      int idx = tid + l * 256;
      int r = idx >> 4, c = (idx & 15) << 2;
      float4 kv = *(const float4*)(Kp + (size_t)(k0 + r) * DK_ + c);
      KPs[r * 64 + ((c + 0) ^ r)] = kv.x;
      KPs[r * 64 + ((c + 1) ^ r)] = kv.y;
      KPs[r * 64 + ((c + 2) ^ r)] = kv.z;
      KPs[r * 64 + ((c + 3) ^ r)] = kv.w;
      *(float4*)&Vs[r * 64 + c] = *(const float4*)(Vp + (size_t)(k0 + r) * DK_ + c);
    }
    __syncthreads();

    // S = Q K^T for this tile (registers)
    float sv[4][4];
#pragma unroll
    for (int i = 0; i < 4; i++)
#pragma unroll
      for (int j = 0; j < 4; j++) sv[i][j] = 0.f;

#pragma unroll 8
    for (int d = 0; d < 64; d++) {
      float av[4], bvv[4];
#pragma unroll
      for (int i = 0; i < 4; i++) av[i] = Qs[(4 * ty + i) * 64 + d];
#pragma unroll
      for (int j = 0; j < 4; j++) {
        int kr = 4 * tx + j;
        bvv[j] = KPs[kr * 64 + (d ^ kr)];
      }
#pragma unroll
      for (int i = 0; i < 4; i++)
#pragma unroll
        for (int j = 0; j < 4; j++) sv[i][j] += av[i] * bvv[j];
    }

    // scale then mask (matches reference order: scores/8 then where(mask==0, -1e10))
#pragma unroll
    for (int i = 0; i < 4; i++) {
      const int4 mm = *(const int4*)(Mp + (size_t)(4 * ty + i) * S_ + k0 + 4 * tx);
      sv[i][0] = (mm.x == 0) ? NEGV : sv[i][0] * 0.125f;
      sv[i][1] = (mm.y == 0) ? NEGV : sv[i][1] * 0.125f;
      sv[i][2] = (mm.z == 0) ? NEGV : sv[i][2] * 0.125f;
      sv[i][3] = (mm.w == 0) ? NEGV : sv[i][3] * 0.125f;
    }

    __syncthreads();  // all K reads done; KPs becomes the P buffer

    // Online softmax (row = query; reduce across the 16 tx lanes of a half-warp)
#pragma unroll
    for (int i = 0; i < 4; i++) {
      float rmax = fmaxf(fmaxf(sv[i][0], sv[i][1]), fmaxf(sv[i][2], sv[i][3]));
#pragma unroll
      for (int off = 8; off > 0; off >>= 1)
        rmax = fmaxf(rmax, __shfl_xor_sync(0xffffffffu, rmax, off));
      float mn = fmaxf(m[i], rmax);
      float sc = __expf(m[i] - mn);
      float rs = 0.f;
      float p[4];
#pragma unroll
      for (int j = 0; j < 4; j++) {
        p[j] = __expf(sv[i][j] - mn);
        rs += p[j];
      }
#pragma unroll
      for (int off = 8; off > 0; off >>= 1)
        rs += __shfl_xor_sync(0xffffffffu, rs, off);
      lsum[i] = lsum[i] * sc + rs;
      m[i] = mn;
#pragma unroll
      for (int j = 0; j < 4; j++) acc[i][j] *= sc;
#pragma unroll
      for (int j = 0; j < 4; j++) KPs[(4 * ty + i) * 64 + 4 * tx + j] = p[j];
    }
    __syncthreads();  // P visible to all

    // O += P V
#pragma unroll 8
    for (int j = 0; j < 64; j++) {
      float4 v4 = *(const float4*)&Vs[j * 64 + 4 * tx];
      float p0 = KPs[(4 * ty + 0) * 64 + j];
      float p1 = KPs[(4 * ty + 1) * 64 + j];
      float p2 = KPs[(4 * ty + 2) * 64 + j];
      float p3 = KPs[(4 * ty + 3) * 64 + j];
      acc[0][0] += p0 * v4.x; acc[0][1] += p0 * v4.y; acc[0][2] += p0 * v4.z; acc[0][3] += p0 * v4.w;
      acc[1][0] += p1 * v4.x; acc[1][1] += p1 * v4.y; acc[1][2] += p1 * v4.z; acc[1][3] += p1 * v4.w;
      acc[2][0] += p2 * v4.x; acc[2][1] += p2 * v4.y; acc[2][2] += p2 * v4.z; acc[2][3] += p2 * v4.w;
      acc[3][0] += p3 * v4.x; acc[3][1] += p3 * v4.y; acc[3][2] += p3 * v4.z; acc[3][3] += p3 * v4.w;
    }
  }

  float* Op = g_Oh + ((size_t)(b * H_ + h) * S_ + qt * 64) * DK_;
#pragma unroll
  for (int i = 0; i < 4; i++) {
    float inv = 1.f / lsum[i];
    *(float4*)(Op + (size_t)(4 * ty + i) * DK_ + 4 * tx) =
        make_float4(acc[i][0] * inv, acc[i][1] * inv, acc[i][2] * inv, acc[i][3] * inv);
  }
}

// ---------------------------------------------------------------------------
extern "C" void kernel_launch(void* const* d_in, const int* in_sizes, int n_in,
                              void* d_out, int out_size) {
  (void)in_sizes; (void)n_in; (void)out_size;
  const float* dec  = (const float*)d_in[0];
  const float* enc  = (const float*)d_in[1];
  const float* Wq   = (const float*)d_in[2];
  const float* Wkv  = (const float*)d_in[3];
  const float* Wo   = (const float*)d_in[4];
  const int*   mask = (const int*)d_in[5];
  float* out = (float*)d_out;

  float *Qp = nullptr, *KVp = nullptr, *attnp = nullptr;
  cudaGetSymbolAddress((void**)&Qp, g_Q);
  cudaGetSymbolAddress((void**)&KVp, g_KV);
  cudaGetSymbolAddress((void**)&attnp, g_attn);

  const int M = B_ * S_;  // 4096
  gemm_nt<<<dim3(DIM_ / 128, M / 128), 256>>>(dec, Wq, Qp, M, DIM_, DIM_);
  gemm_nt<<<dim3(2 * DIM_ / 128, M / 128), 256>>>(enc, Wkv, KVp, M, 2 * DIM_, DIM_);
  repack_qkv<<<M, 256>>>();
  attn_kernel<<<dim3(S_ / 64, H_, B_), 256>>>(mask);
  unpack_o<<<M, 256>>>();
  gemm_nt<<<dim3(DIM_ / 128, M / 128), 256>>>(attnp, Wo, out, M, DIM_, DIM_);
}

// round 6
// speedup vs baseline: 1.3633x; 1.3633x over previous
#include <cuda_runtime.h>
#include <cuda_bf16.h>
#include <math_constants.h>
#include <cstdint>

// CrossMHA: B=2, S=2048, DIM=1024, H=16, DK=64, heads-last layout [b,s,dk,h]
namespace {
constexpr int B_ = 2, S_ = 2048, DIM_ = 1024, H_ = 16, DK_ = 64;
constexpr float NEGV = -10000000000.0f;
}

// Scratch (static device globals; no allocation in kernel_launch)
__device__ float g_Q[B_ * S_ * DIM_];        // dec @ Wq^T, [b,s,dim]
__device__ float g_KV[B_ * S_ * 2 * DIM_];   // enc @ Wkv^T, [b,s,2*dim]
__device__ float g_Qh[B_ * S_ * DIM_];       // [b,h,s,dk]
__device__ float g_Kh[B_ * S_ * DIM_];
__device__ float g_Vh[B_ * S_ * DIM_];
__device__ float g_Oh[B_ * S_ * DIM_];       // attention out, [b,h,s,dk]
__device__ float g_attn[B_ * S_ * DIM_];     // repacked to [b,s,dim] heads-last

// ===========================================================================
// Warp-level bf16 MMA helpers (base sm_80+ instructions; assemble on sm_103)
// ===========================================================================
__device__ __forceinline__ uint32_t packbf(__nv_bfloat16 lo, __nv_bfloat16 hi) {
  __nv_bfloat162 t(lo, hi);   // .x = low 16 bits (k even), .y = high (k odd)
  return *reinterpret_cast<uint32_t*>(&t);
}
// split a pair of fp32 into bf16-hi pair and bf16-lo (residual) pair
__device__ __forceinline__ void split2(float x, float y, uint32_t& hi, uint32_t& lo) {
  __nv_bfloat16 bx = __float2bfloat16_rn(x);
  __nv_bfloat16 by = __float2bfloat16_rn(y);
  float rx = x - __bfloat162float(bx);
  float ry = y - __bfloat162float(by);
  hi = packbf(bx, by);
  lo = packbf(__float2bfloat16_rn(rx), __float2bfloat16_rn(ry));
}
// D += A(16x16, row-major) * B(16x8, col-major), f32 accum
__device__ __forceinline__ void mma16816(float* d, const uint32_t* a, const uint32_t* b) {
  asm volatile(
      "mma.sync.aligned.m16n8k16.row.col.f32.bf16.bf16.f32 "
      "{%0,%1,%2,%3}, {%4,%5,%6,%7}, {%8,%9}, {%0,%1,%2,%3};"
      : "+f"(d[0]), "+f"(d[1]), "+f"(d[2]), "+f"(d[3])
      : "r"(a[0]), "r"(a[1]), "r"(a[2]), "r"(a[3]), "r"(b[0]), "r"(b[1]));
}

// ===========================================================================
// bf16-split GEMM on mma.sync: C[M,N] = A[M,K] * W[N,K]^T  (fp32 in/out)
// Block tile 128x128, 8 warps (2 in M x 4 in N), warp tile 64x32.
// K-chunk 64. 3-MMA emulation: Ahi*Whi + Ahi*Wlo + Alo*Whi.
// SMEM rows: 64 bf16 (=32 b32) data + stride 36 b32 (144B): (g*36+t) mod 32
// == 4g+t == lane  ->  conflict-free fragment loads.
// ===========================================================================
namespace {
constexpr int GK = 1024;               // K (fixed for all 3 GEMMs)
constexpr int NCHUNK = GK / 64;        // 16
constexpr int R4 = 36;                 // smem row stride in b32 (144 bytes)
constexpr int TILE32 = 128 * R4;       // 4608 b32 = 18432 B per tile component
constexpr int GEMM_SMEM = 4 * TILE32 * 4;  // Ahi,Alo,Whi,Wlo = 73728 B
}

__global__ __launch_bounds__(256, 2)
void gemm_tc(const float* __restrict__ A, const float* __restrict__ W,
             float* __restrict__ C, int N) {
  extern __shared__ uint32_t sm[];
  uint32_t* const sAhi = sm;
  uint32_t* const sAlo = sm + TILE32;
  uint32_t* const sWhi = sm + 2 * TILE32;
  uint32_t* const sWlo = sm + 3 * TILE32;

  const int tid = threadIdx.x;
  const int lane = tid & 31;
  const int wid = tid >> 5;
  const int g = lane >> 2;      // 0..7
  const int t = lane & 3;       // 0..3
  const int warp_m = wid & 1;   // 0..1  (64 rows each)
  const int warp_n = wid >> 1;  // 0..3  (32 cols each)
  const int bm = blockIdx.y * 128;
  const int bn = blockIdx.x * 128;

  float acc[4][4][4];           // [mt][nt][c0..c3]
#pragma unroll
  for (int mt = 0; mt < 4; mt++)
#pragma unroll
    for (int nt = 0; nt < 4; nt++)
#pragma unroll
      for (int c = 0; c < 4; c++) acc[mt][nt][c] = 0.f;

  const uint32_t* const Awhi = sAhi + (warp_m * 64) * R4;
  const uint32_t* const Awlo = sAlo + (warp_m * 64) * R4;
  const uint32_t* const Bwhi = sWhi + (warp_n * 32) * R4;
  const uint32_t* const Bwlo = sWlo + (warp_n * 32) * R4;

  for (int ch = 0; ch < NCHUNK; ++ch) {
    const int k0 = ch * 64;
    // ---- gmem loads (fp32, coalesced float4) ----
    float4 av[8], wv[8];
#pragma unroll
    for (int l = 0; l < 8; ++l) {
      int idx = tid + l * 256;       // 0..2047
      int r = idx >> 4;              // 0..127
      int c4 = idx & 15;             // float4 within the 64-wide row
      av[l] = *(const float4*)(A + (size_t)(bm + r) * GK + k0 + c4 * 4);
      wv[l] = *(const float4*)(W + (size_t)(bn + r) * GK + k0 + c4 * 4);
    }
    __syncthreads();   // previous chunk's compute done with smem
    // ---- split to bf16 hi/lo, store to smem ----
#pragma unroll
    for (int l = 0; l < 8; ++l) {
      int idx = tid + l * 256;
      int r = idx >> 4;
      int c4 = idx & 15;
      int base = r * R4 + c4 * 2;
      uint32_t h0, l0, h1, l1;
      split2(av[l].x, av[l].y, h0, l0);
      split2(av[l].z, av[l].w, h1, l1);
      sAhi[base] = h0; sAhi[base + 1] = h1;
      sAlo[base] = l0; sAlo[base + 1] = l1;
      split2(wv[l].x, wv[l].y, h0, l0);
      split2(wv[l].z, wv[l].w, h1, l1);
      sWhi[base] = h0; sWhi[base + 1] = h1;
      sWlo[base] = l0; sWlo[base + 1] = l1;
    }
    __syncthreads();
    // ---- 4 x k16 MMA steps ----
#pragma unroll
    for (int ks = 0; ks < 4; ++ks) {
      const int kb = ks * 8;   // b32 offset of this k16 slice
      // B fragments for all 4 n-tiles (hi and lo)
      uint32_t bh[4][2], bl[4][2];
#pragma unroll
      for (int nt = 0; nt < 4; ++nt) {
        int o = (nt * 8 + g) * R4 + kb + t;
        bh[nt][0] = Bwhi[o]; bh[nt][1] = Bwhi[o + 4];
        bl[nt][0] = Bwlo[o]; bl[nt][1] = Bwlo[o + 4];
      }
#pragma unroll
      for (int mt = 0; mt < 4; ++mt) {
        int o0 = (mt * 16 + g) * R4 + kb + t;
        int o1 = o0 + 8 * R4;
        uint32_t ah[4], al[4];
        ah[0] = Awhi[o0]; ah[1] = Awhi[o1]; ah[2] = Awhi[o0 + 4]; ah[3] = Awhi[o1 + 4];
        al[0] = Awlo[o0]; al[1] = Awlo[o1]; al[2] = Awlo[o0 + 4]; al[3] = Awlo[o1 + 4];
#pragma unroll
        for (int nt = 0; nt < 4; ++nt) {
          mma16816(acc[mt][nt], ah, bh[nt]);
          mma16816(acc[mt][nt], ah, bl[nt]);
          mma16816(acc[mt][nt], al, bh[nt]);
        }
      }
    }
  }

  // ---- epilogue ----
#pragma unroll
  for (int mt = 0; mt < 4; ++mt) {
    int row0 = bm + warp_m * 64 + mt * 16 + g;
#pragma unroll
    for (int nt = 0; nt < 4; ++nt) {
      int col = bn + warp_n * 32 + nt * 8 + 2 * t;
      *(float2*)(C + (size_t)row0 * N + col) = make_float2(acc[mt][nt][0], acc[mt][nt][1]);
      *(float2*)(C + (size_t)(row0 + 8) * N + col) = make_float2(acc[mt][nt][2], acc[mt][nt][3]);
    }
  }
}

// ---------------------------------------------------------------------------
// Repack: [b,s, d*16+h] -> [b,h,s,d] for Q, K, V. One block per (b,s) row.
// ---------------------------------------------------------------------------
__global__ void repack_qkv() {
  __shared__ float bq[1056], bk[1056], bv[1056];  // 1024 + 32 pad slots
  const int bs = blockIdx.x;
  const int b = bs >> 11;          // /S_
  const int s = bs & (S_ - 1);
  const int tid = threadIdx.x;
  const float* qrow  = g_Q  + (size_t)bs * DIM_;
  const float* kvrow = g_KV + (size_t)bs * 2 * DIM_;
#pragma unroll
  for (int l = 0; l < 4; l++) {
    int i = tid + l * 256;
    bq[i + (i >> 5)] = qrow[i];
    bk[i + (i >> 5)] = kvrow[i];
    bv[i + (i >> 5)] = kvrow[DIM_ + i];
  }
  __syncthreads();
#pragma unroll
  for (int l = 0; l < 4; l++) {
    int idx = tid + l * 256;
    int h = idx >> 6, d = idx & 63;
    int a = d * H_ + h;
    a += a >> 5;
    size_t o = ((size_t)(b * H_ + h) * S_ + s) * DK_ + d;
    g_Qh[o] = bq[a];
    g_Kh[o] = bk[a];
    g_Vh[o] = bv[a];
  }
}

// ---------------------------------------------------------------------------
// Unpack: [b,h,s,d] -> [b,s, d*16+h]
// ---------------------------------------------------------------------------
__global__ void unpack_o() {
  __shared__ float buf[1056];
  const int bs = blockIdx.x;
  const int b = bs >> 11;
  const int s = bs & (S_ - 1);
  const int tid = threadIdx.x;
#pragma unroll
  for (int l = 0; l < 4; l++) {
    int idx = tid + l * 256;
    int h = idx >> 6, d = idx & 63;
    int a = d * H_ + h;
    buf[a + (a >> 5)] = g_Oh[((size_t)(b * H_ + h) * S_ + s) * DK_ + d];
  }
  __syncthreads();
#pragma unroll
  for (int l = 0; l < 4; l++) {
    int i = tid + l * 256;
    g_attn[(size_t)bs * DIM_ + i] = buf[i + (i >> 5)];
  }
}

// ---------------------------------------------------------------------------
// Flash attention per (b, h, 64-query tile). 64x64 key tiles, 4x4 per thread.
// ---------------------------------------------------------------------------
__global__ __launch_bounds__(256, 2)
void attn_kernel(const int* __restrict__ mask) {
  __shared__ float Qs[64 * 64];
  __shared__ float KPs[64 * 64];   // K (skewed), later P (plain)
  __shared__ float Vs[64 * 64];

  const int qt = blockIdx.x, h = blockIdx.y, b = blockIdx.z;
  const int tid = threadIdx.x, tx = tid & 15, ty = tid >> 4;
  const float* Qp = g_Qh + ((size_t)(b * H_ + h) * S_ + qt * 64) * DK_;
  const float* Kp = g_Kh + (size_t)(b * H_ + h) * S_ * DK_;
  const float* Vp = g_Vh + (size_t)(b * H_ + h) * S_ * DK_;
  const int*   Mp = mask + ((size_t)b * S_ + qt * 64) * S_;

#pragma unroll
  for (int l = 0; l < 4; l++) {
    int idx = tid + l * 256;
    int r = idx >> 4, c = (idx & 15) << 2;
    *(float4*)&Qs[r * 64 + c] = *(const float4*)(Qp + r * DK_ + c);
  }

  float m[4], lsum[4], acc[4][4];
#pragma unroll
  for (int i = 0; i < 4; i++) {
    m[i] = -CUDART_INF_F;
    lsum[i] = 0.f;
#pragma unroll
    for (int j = 0; j < 4; j++) acc[i][j] = 0.f;
  }

  for (int k0 = 0; k0 < S_; k0 += 64) {
    __syncthreads();
#pragma unroll
    for (int l = 0; l < 4; l++) {
      int idx = tid + l * 256;
      int r = idx >> 4, c = (idx & 15) << 2;
      float4 kv = *(const float4*)(Kp + (size_t)(k0 + r) * DK_ + c);
      KPs[r * 64 + ((c + 0) ^ r)] = kv.x;
      KPs[r * 64 + ((c + 1) ^ r)] = kv.y;
      KPs[r * 64 + ((c + 2) ^ r)] = kv.z;
      KPs[r * 64 + ((c + 3) ^ r)] = kv.w;
      *(float4*)&Vs[r * 64 + c] = *(const float4*)(Vp + (size_t)(k0 + r) * DK_ + c);
    }
    __syncthreads();

    float sv[4][4];
#pragma unroll
    for (int i = 0; i < 4; i++)
#pragma unroll
      for (int j = 0; j < 4; j++) sv[i][j] = 0.f;

#pragma unroll 8
    for (int d = 0; d < 64; d++) {
      float av[4], bvv[4];
#pragma unroll
      for (int i = 0; i < 4; i++) av[i] = Qs[(4 * ty + i) * 64 + d];
#pragma unroll
      for (int j = 0; j < 4; j++) {
        int kr = 4 * tx + j;
        bvv[j] = KPs[kr * 64 + (d ^ kr)];
      }
#pragma unroll
      for (int i = 0; i < 4; i++)
#pragma unroll
        for (int j = 0; j < 4; j++) sv[i][j] += av[i] * bvv[j];
    }

#pragma unroll
    for (int i = 0; i < 4; i++) {
      const int4 mm = *(const int4*)(Mp + (size_t)(4 * ty + i) * S_ + k0 + 4 * tx);
      sv[i][0] = (mm.x == 0) ? NEGV : sv[i][0] * 0.125f;
      sv[i][1] = (mm.y == 0) ? NEGV : sv[i][1] * 0.125f;
      sv[i][2] = (mm.z == 0) ? NEGV : sv[i][2] * 0.125f;
      sv[i][3] = (mm.w == 0) ? NEGV : sv[i][3] * 0.125f;
    }

    __syncthreads();  // all K reads done; KPs becomes the P buffer

#pragma unroll
    for (int i = 0; i < 4; i++) {
      float rmax = fmaxf(fmaxf(sv[i][0], sv[i][1]), fmaxf(sv[i][2], sv[i][3]));
#pragma unroll
      for (int off = 8; off > 0; off >>= 1)
        rmax = fmaxf(rmax, __shfl_xor_sync(0xffffffffu, rmax, off));
      float mn = fmaxf(m[i], rmax);
      float sc = __expf(m[i] - mn);
      float rs = 0.f;
      float p[4];
#pragma unroll
      for (int j = 0; j < 4; j++) {
        p[j] = __expf(sv[i][j] - mn);
        rs += p[j];
      }
#pragma unroll
      for (int off = 8; off > 0; off >>= 1)
        rs += __shfl_xor_sync(0xffffffffu, rs, off);
      lsum[i] = lsum[i] * sc + rs;
      m[i] = mn;
#pragma unroll
      for (int j = 0; j < 4; j++) acc[i][j] *= sc;
#pragma unroll
      for (int j = 0; j < 4; j++) KPs[(4 * ty + i) * 64 + 4 * tx + j] = p[j];
    }
    __syncthreads();

#pragma unroll 8
    for (int j = 0; j < 64; j++) {
      float4 v4 = *(const float4*)&Vs[j * 64 + 4 * tx];
      float p0 = KPs[(4 * ty + 0) * 64 + j];
      float p1 = KPs[(4 * ty + 1) * 64 + j];
      float p2 = KPs[(4 * ty + 2) * 64 + j];
      float p3 = KPs[(4 * ty + 3) * 64 + j];
      acc[0][0] += p0 * v4.x; acc[0][1] += p0 * v4.y; acc[0][2] += p0 * v4.z; acc[0][3] += p0 * v4.w;
      acc[1][0] += p1 * v4.x; acc[1][1] += p1 * v4.y; acc[1][2] += p1 * v4.z; acc[1][3] += p1 * v4.w;
      acc[2][0] += p2 * v4.x; acc[2][1] += p2 * v4.y; acc[2][2] += p2 * v4.z; acc[2][3] += p2 * v4.w;
      acc[3][0] += p3 * v4.x; acc[3][1] += p3 * v4.y; acc[3][2] += p3 * v4.z; acc[3][3] += p3 * v4.w;
    }
  }

  float* Op = g_Oh + ((size_t)(b * H_ + h) * S_ + qt * 64) * DK_;
#pragma unroll
  for (int i = 0; i < 4; i++) {
    float inv = 1.f / lsum[i];
    *(float4*)(Op + (size_t)(4 * ty + i) * DK_ + 4 * tx) =
        make_float4(acc[i][0] * inv, acc[i][1] * inv, acc[i][2] * inv, acc[i][3] * inv);
  }
}

// ---------------------------------------------------------------------------
extern "C" void kernel_launch(void* const* d_in, const int* in_sizes, int n_in,
                              void* d_out, int out_size) {
  (void)in_sizes; (void)n_in; (void)out_size;
  const float* dec  = (const float*)d_in[0];
  const float* enc  = (const float*)d_in[1];
  const float* Wq   = (const float*)d_in[2];
  const float* Wkv  = (const float*)d_in[3];
  const float* Wo   = (const float*)d_in[4];
  const int*   mask = (const int*)d_in[5];
  float* out = (float*)d_out;

  float *Qp = nullptr, *KVp = nullptr, *attnp = nullptr;
  cudaGetSymbolAddress((void**)&Qp, g_Q);
  cudaGetSymbolAddress((void**)&KVp, g_KV);
  cudaGetSymbolAddress((void**)&attnp, g_attn);

  cudaFuncSetAttribute(gemm_tc, cudaFuncAttributeMaxDynamicSharedMemorySize, GEMM_SMEM);

  const int M = B_ * S_;  // 4096
  gemm_tc<<<dim3(DIM_ / 128, M / 128), 256, GEMM_SMEM>>>(dec, Wq, Qp, DIM_);
  gemm_tc<<<dim3(2 * DIM_ / 128, M / 128), 256, GEMM_SMEM>>>(enc, Wkv, KVp, 2 * DIM_);
  repack_qkv<<<M, 256>>>();
  attn_kernel<<<dim3(S_ / 64, H_, B_), 256>>>(mask);
  unpack_o<<<M, 256>>>();
  gemm_tc<<<dim3(DIM_ / 128, M / 128), 256, GEMM_SMEM>>>(attnp, Wo, out, DIM_);
}

// round 7
// speedup vs baseline: 2.3750x; 1.7421x over previous
#include <cuda_runtime.h>
#include <cuda_bf16.h>
#include <math_constants.h>
#include <cstdint>

// CrossMHA: B=2, S=2048, DIM=1024, H=16, DK=64, heads-last layout [b,s,dk,h]
namespace {
constexpr int B_ = 2, S_ = 2048, DIM_ = 1024, H_ = 16, DK_ = 64;
constexpr float NEGV = -10000000000.0f;
}

// Scratch (static device globals; no allocation in kernel_launch)
__device__ float g_Q[B_ * S_ * DIM_];        // dec @ Wq^T, [b,s,dim]
__device__ float g_KV[B_ * S_ * 2 * DIM_];   // enc @ Wkv^T, [b,s,2*dim]
__device__ float g_Qh[B_ * S_ * DIM_];       // [b,h,s,dk]
__device__ float g_Kh[B_ * S_ * DIM_];
__device__ float g_Vh[B_ * S_ * DIM_];
__device__ float g_Oh[B_ * S_ * DIM_];       // attention out, [b,h,s,dk]
__device__ float g_attn[B_ * S_ * DIM_];     // repacked to [b,s,dim] heads-last

// ===========================================================================
// Warp-level bf16 MMA helpers (base sm_80+ instructions; assemble on sm_103)
// ===========================================================================
__device__ __forceinline__ uint32_t packbf(__nv_bfloat16 lo, __nv_bfloat16 hi) {
  __nv_bfloat162 t(lo, hi);   // .x = low 16 bits (k even), .y = high (k odd)
  return *reinterpret_cast<uint32_t*>(&t);
}
// split a pair of fp32 into bf16-hi pair and bf16-lo (residual) pair
__device__ __forceinline__ void split2(float x, float y, uint32_t& hi, uint32_t& lo) {
  __nv_bfloat16 bx = __float2bfloat16_rn(x);
  __nv_bfloat16 by = __float2bfloat16_rn(y);
  float rx = x - __bfloat162float(bx);
  float ry = y - __bfloat162float(by);
  hi = packbf(bx, by);
  lo = packbf(__float2bfloat16_rn(rx), __float2bfloat16_rn(ry));
}
// D += A(16x16, row-major) * B(16x8, col-major), f32 accum
__device__ __forceinline__ void mma16816(float* d, const uint32_t* a, const uint32_t* b) {
  asm volatile(
      "mma.sync.aligned.m16n8k16.row.col.f32.bf16.bf16.f32 "
      "{%0,%1,%2,%3}, {%4,%5,%6,%7}, {%8,%9}, {%0,%1,%2,%3};"
      : "+f"(d[0]), "+f"(d[1]), "+f"(d[2]), "+f"(d[3])
      : "r"(a[0]), "r"(a[1]), "r"(a[2]), "r"(a[3]), "r"(b[0]), "r"(b[1]));
}

// ===========================================================================
// bf16-split GEMM on mma.sync: C[M,N] = A[M,K] * W[N,K]^T  (fp32 in/out)
// Block tile 128x128, 8 warps (2 in M x 4 in N), warp tile 64x32.
// ===========================================================================
namespace {
constexpr int GK = 1024;               // K (fixed for all 3 GEMMs)
constexpr int NCHUNK = GK / 64;        // 16
constexpr int R4 = 36;                 // smem row stride in b32 (144 bytes)
constexpr int TILE32 = 128 * R4;       // 4608 b32
constexpr int GEMM_SMEM = 4 * TILE32 * 4;  // 73728 B
}

__global__ __launch_bounds__(256, 2)
void gemm_tc(const float* __restrict__ A, const float* __restrict__ W,
             float* __restrict__ C, int N) {
  extern __shared__ uint32_t sm[];
  uint32_t* const sAhi = sm;
  uint32_t* const sAlo = sm + TILE32;
  uint32_t* const sWhi = sm + 2 * TILE32;
  uint32_t* const sWlo = sm + 3 * TILE32;

  const int tid = threadIdx.x;
  const int lane = tid & 31;
  const int wid = tid >> 5;
  const int g = lane >> 2;
  const int t = lane & 3;
  const int warp_m = wid & 1;
  const int warp_n = wid >> 1;
  const int bm = blockIdx.y * 128;
  const int bn = blockIdx.x * 128;

  float acc[4][4][4];
#pragma unroll
  for (int mt = 0; mt < 4; mt++)
#pragma unroll
    for (int nt = 0; nt < 4; nt++)
#pragma unroll
      for (int c = 0; c < 4; c++) acc[mt][nt][c] = 0.f;

  const uint32_t* const Awhi = sAhi + (warp_m * 64) * R4;
  const uint32_t* const Awlo = sAlo + (warp_m * 64) * R4;
  const uint32_t* const Bwhi = sWhi + (warp_n * 32) * R4;
  const uint32_t* const Bwlo = sWlo + (warp_n * 32) * R4;

  for (int ch = 0; ch < NCHUNK; ++ch) {
    const int k0 = ch * 64;
    float4 av[8], wv[8];
#pragma unroll
    for (int l = 0; l < 8; ++l) {
      int idx = tid + l * 256;
      int r = idx >> 4;
      int c4 = idx & 15;
      av[l] = *(const float4*)(A + (size_t)(bm + r) * GK + k0 + c4 * 4);
      wv[l] = *(const float4*)(W + (size_t)(bn + r) * GK + k0 + c4 * 4);
    }
    __syncthreads();
#pragma unroll
    for (int l = 0; l < 8; ++l) {
      int idx = tid + l * 256;
      int r = idx >> 4;
      int c4 = idx & 15;
      int base = r * R4 + c4 * 2;
      uint32_t h0, l0, h1, l1;
      split2(av[l].x, av[l].y, h0, l0);
      split2(av[l].z, av[l].w, h1, l1);
      sAhi[base] = h0; sAhi[base + 1] = h1;
      sAlo[base] = l0; sAlo[base + 1] = l1;
      split2(wv[l].x, wv[l].y, h0, l0);
      split2(wv[l].z, wv[l].w, h1, l1);
      sWhi[base] = h0; sWhi[base + 1] = h1;
      sWlo[base] = l0; sWlo[base + 1] = l1;
    }
    __syncthreads();
#pragma unroll
    for (int ks = 0; ks < 4; ++ks) {
      const int kb = ks * 8;
      uint32_t bh[4][2], bl[4][2];
#pragma unroll
      for (int nt = 0; nt < 4; ++nt) {
        int o = (nt * 8 + g) * R4 + kb + t;
        bh[nt][0] = Bwhi[o]; bh[nt][1] = Bwhi[o + 4];
        bl[nt][0] = Bwlo[o]; bl[nt][1] = Bwlo[o + 4];
      }
#pragma unroll
      for (int mt = 0; mt < 4; ++mt) {
        int o0 = (mt * 16 + g) * R4 + kb + t;
        int o1 = o0 + 8 * R4;
        uint32_t ah[4], al[4];
        ah[0] = Awhi[o0]; ah[1] = Awhi[o1]; ah[2] = Awhi[o0 + 4]; ah[3] = Awhi[o1 + 4];
        al[0] = Awlo[o0]; al[1] = Awlo[o1]; al[2] = Awlo[o0 + 4]; al[3] = Awlo[o1 + 4];
#pragma unroll
        for (int nt = 0; nt < 4; ++nt) {
          mma16816(acc[mt][nt], ah, bh[nt]);
          mma16816(acc[mt][nt], ah, bl[nt]);
          mma16816(acc[mt][nt], al, bh[nt]);
        }
      }
    }
  }

#pragma unroll
  for (int mt = 0; mt < 4; ++mt) {
    int row0 = bm + warp_m * 64 + mt * 16 + g;
#pragma unroll
    for (int nt = 0; nt < 4; ++nt) {
      int col = bn + warp_n * 32 + nt * 8 + 2 * t;
      *(float2*)(C + (size_t)row0 * N + col) = make_float2(acc[mt][nt][0], acc[mt][nt][1]);
      *(float2*)(C + (size_t)(row0 + 8) * N + col) = make_float2(acc[mt][nt][2], acc[mt][nt][3]);
    }
  }
}

// ---------------------------------------------------------------------------
// Repack: [b,s, d*16+h] -> [b,h,s,d] for Q, K, V. One block per (b,s) row.
// ---------------------------------------------------------------------------
__global__ void repack_qkv() {
  __shared__ float bq[1056], bk[1056], bv[1056];
  const int bs = blockIdx.x;
  const int b = bs >> 11;
  const int s = bs & (S_ - 1);
  const int tid = threadIdx.x;
  const float* qrow  = g_Q  + (size_t)bs * DIM_;
  const float* kvrow = g_KV + (size_t)bs * 2 * DIM_;
#pragma unroll
  for (int l = 0; l < 4; l++) {
    int i = tid + l * 256;
    bq[i + (i >> 5)] = qrow[i];
    bk[i + (i >> 5)] = kvrow[i];
    bv[i + (i >> 5)] = kvrow[DIM_ + i];
  }
  __syncthreads();
#pragma unroll
  for (int l = 0; l < 4; l++) {
    int idx = tid + l * 256;
    int h = idx >> 6, d = idx & 63;
    int a = d * H_ + h;
    a += a >> 5;
    size_t o = ((size_t)(b * H_ + h) * S_ + s) * DK_ + d;
    g_Qh[o] = bq[a];
    g_Kh[o] = bk[a];
    g_Vh[o] = bv[a];
  }
}

// ---------------------------------------------------------------------------
// Unpack: [b,h,s,d] -> [b,s, d*16+h]
// ---------------------------------------------------------------------------
__global__ void unpack_o() {
  __shared__ float buf[1056];
  const int bs = blockIdx.x;
  const int b = bs >> 11;
  const int s = bs & (S_ - 1);
  const int tid = threadIdx.x;
#pragma unroll
  for (int l = 0; l < 4; l++) {
    int idx = tid + l * 256;
    int h = idx >> 6, d = idx & 63;
    int a = d * H_ + h;
    buf[a + (a >> 5)] = g_Oh[((size_t)(b * H_ + h) * S_ + s) * DK_ + d];
  }
  __syncthreads();
#pragma unroll
  for (int l = 0; l < 4; l++) {
    int i = tid + l * 256;
    g_attn[(size_t)bs * DIM_ + i] = buf[i + (i >> 5)];
  }
}

// ===========================================================================
// Tensor-core flash attention. Block = 128 threads (4 warps), 64 q rows.
// Warp w: q rows [16w, 16w+16). Key tiles of 64. QK^T: 3-MMA hi/lo split.
// Softmax in register fragments (D-frag of S == A-frag of P for PV).
// PV: P hi/lo split x V hi/lo: Phi*Vhi + Phi*Vlo + Plo*Vhi.
// SMEM: Q/K bf16 pairs along dk, row stride 36 u32 (bank=4g+t, clean).
//       V bf16 pairs along key, row stride 72 u32 (bank=8t+g, clean).
// ===========================================================================
namespace {
constexpr int ATTN_SMEM = 6 * 2304 * 4;  // 55296 B
}

__global__ __launch_bounds__(128)
void attn_mma(const int* __restrict__ mask) {
  extern __shared__ uint32_t asm_[];
  uint32_t* const Qhi = asm_;
  uint32_t* const Qlo = asm_ + 2304;
  uint32_t* const Khi = asm_ + 2 * 2304;
  uint32_t* const Klo = asm_ + 3 * 2304;
  uint32_t* const Vhp = asm_ + 4 * 2304;   // [32][72] packed pairs along key
  uint32_t* const Vlp = asm_ + 5 * 2304;

  const int qt = blockIdx.x, h = blockIdx.y, b = blockIdx.z;
  const int tid = threadIdx.x;
  const int lane = tid & 31, w = tid >> 5;
  const int g = lane >> 2, t = lane & 3;
  const float* Qp = g_Qh + ((size_t)(b * H_ + h) * S_ + qt * 64) * DK_;
  const float* Kp = g_Kh + (size_t)(b * H_ + h) * S_ * DK_;
  const float* Vp = g_Vh + (size_t)(b * H_ + h) * S_ * DK_;
  const int*   Mp = mask + ((size_t)b * S_ + qt * 64) * S_;

  // ---- load Q tile once: [64][64] f32 -> packed pairs along dk ----
  {
    int r = tid >> 1, hf = tid & 1;
    const float* src = Qp + r * DK_ + hf * 32;
#pragma unroll
    for (int i = 0; i < 8; i++) {
      float4 v = *(const float4*)(src + i * 4);
      int dd = r * R4 + hf * 16 + i * 2;
      uint32_t h0, l0, h1, l1;
      split2(v.x, v.y, h0, l0);
      split2(v.z, v.w, h1, l1);
      *(uint2*)&Qhi[dd] = make_uint2(h0, h1);
      *(uint2*)&Qlo[dd] = make_uint2(l0, l1);
    }
  }

  float m0 = -CUDART_INF_F, m1 = -CUDART_INF_F, ls0 = 0.f, ls1 = 0.f;
  float oacc[8][4];
#pragma unroll
  for (int jd = 0; jd < 8; jd++)
#pragma unroll
    for (int c = 0; c < 4; c++) oacc[jd][c] = 0.f;

  const uint32_t* const Qbh = Qhi + (w * 16) * R4;
  const uint32_t* const Qbl = Qlo + (w * 16) * R4;
  const int r0 = qt * 64 + w * 16 + g;   // global q row (first of pair)

  for (int k0 = 0; k0 < S_; k0 += 64) {
    __syncthreads();   // prior MMAs done with K/V smem (also orders Q on iter 0)
    // ---- load K tile ----
    {
      int r = tid >> 1, hf = tid & 1;
      const float* src = Kp + (size_t)(k0 + r) * DK_ + hf * 32;
#pragma unroll
      for (int i = 0; i < 8; i++) {
        float4 v = *(const float4*)(src + i * 4);
        int dd = r * R4 + hf * 16 + i * 2;
        uint32_t h0, l0, h1, l1;
        split2(v.x, v.y, h0, l0);
        split2(v.z, v.w, h1, l1);
        *(uint2*)&Khi[dd] = make_uint2(h0, h1);
        *(uint2*)&Klo[dd] = make_uint2(l0, l1);
      }
    }
    // ---- load V tile, pack pairs along key ----
    {
      int kk = tid >> 2, q4 = tid & 3;
      const float* s0 = Vp + (size_t)(k0 + 2 * kk) * DK_ + q4 * 16;
      const float* s1 = s0 + DK_;
      int base = kk * 72 + q4 * 16;
#pragma unroll
      for (int i = 0; i < 4; i++) {
        float4 a = *(const float4*)(s0 + i * 4);
        float4 c = *(const float4*)(s1 + i * 4);
        uint32_t hh[4], ll[4];
        split2(a.x, c.x, hh[0], ll[0]);
        split2(a.y, c.y, hh[1], ll[1]);
        split2(a.z, c.z, hh[2], ll[2]);
        split2(a.w, c.w, hh[3], ll[3]);
        *(uint4*)&Vhp[base + i * 4] = make_uint4(hh[0], hh[1], hh[2], hh[3]);
        *(uint4*)&Vlp[base + i * 4] = make_uint4(ll[0], ll[1], ll[2], ll[3]);
      }
    }
    __syncthreads();

    // ---- S = Q K^T (3-MMA split) ----
    float sf[8][4];
#pragma unroll
    for (int j = 0; j < 8; j++)
#pragma unroll
      for (int c = 0; c < 4; c++) sf[j][c] = 0.f;

#pragma unroll
    for (int ks = 0; ks < 4; ++ks) {
      const int kb = ks * 8;
      uint32_t ah[4], al[4];
      ah[0] = Qbh[g * R4 + kb + t];       ah[1] = Qbh[(g + 8) * R4 + kb + t];
      ah[2] = Qbh[g * R4 + kb + t + 4];   ah[3] = Qbh[(g + 8) * R4 + kb + t + 4];
      al[0] = Qbl[g * R4 + kb + t];       al[1] = Qbl[(g + 8) * R4 + kb + t];
      al[2] = Qbl[g * R4 + kb + t + 4];   al[3] = Qbl[(g + 8) * R4 + kb + t + 4];
#pragma unroll
      for (int j = 0; j < 8; j++) {
        int o = (j * 8 + g) * R4 + kb + t;
        uint32_t bh[2] = {Khi[o], Khi[o + 4]};
        uint32_t bl[2] = {Klo[o], Klo[o + 4]};
        mma16816(sf[j], ah, bh);
        mma16816(sf[j], ah, bl);
        mma16816(sf[j], al, bh);
      }
    }

    // ---- scale + mask ----
#pragma unroll
    for (int j = 0; j < 8; j++) {
      int col = k0 + j * 8 + 2 * t;
      int2 ma = *(const int2*)(Mp + (size_t)(w * 16 + g) * S_ + col);
      int2 mb = *(const int2*)(Mp + (size_t)(w * 16 + g + 8) * S_ + col);
      sf[j][0] = ma.x ? sf[j][0] * 0.125f : NEGV;
      sf[j][1] = ma.y ? sf[j][1] * 0.125f : NEGV;
      sf[j][2] = mb.x ? sf[j][2] * 0.125f : NEGV;
      sf[j][3] = mb.y ? sf[j][3] * 0.125f : NEGV;
    }

    // ---- online softmax (rows g and g+8; reduce across the 4 t-lanes) ----
    float rm0 = -CUDART_INF_F, rm1 = -CUDART_INF_F;
#pragma unroll
    for (int j = 0; j < 8; j++) {
      rm0 = fmaxf(rm0, fmaxf(sf[j][0], sf[j][1]));
      rm1 = fmaxf(rm1, fmaxf(sf[j][2], sf[j][3]));
    }
    rm0 = fmaxf(rm0, __shfl_xor_sync(0xffffffffu, rm0, 1));
    rm0 = fmaxf(rm0, __shfl_xor_sync(0xffffffffu, rm0, 2));
    rm1 = fmaxf(rm1, __shfl_xor_sync(0xffffffffu, rm1, 1));
    rm1 = fmaxf(rm1, __shfl_xor_sync(0xffffffffu, rm1, 2));
    float mn0 = fmaxf(m0, rm0), mn1 = fmaxf(m1, rm1);
    float c0 = __expf(m0 - mn0), c1 = __expf(m1 - mn1);
    m0 = mn0; m1 = mn1;
    float rs0 = 0.f, rs1 = 0.f;
#pragma unroll
    for (int j = 0; j < 8; j++) {
      sf[j][0] = __expf(sf[j][0] - mn0);
      sf[j][1] = __expf(sf[j][1] - mn0);
      sf[j][2] = __expf(sf[j][2] - mn1);
      sf[j][3] = __expf(sf[j][3] - mn1);
      rs0 += sf[j][0] + sf[j][1];
      rs1 += sf[j][2] + sf[j][3];
    }
    rs0 += __shfl_xor_sync(0xffffffffu, rs0, 1);
    rs0 += __shfl_xor_sync(0xffffffffu, rs0, 2);
    rs1 += __shfl_xor_sync(0xffffffffu, rs1, 1);
    rs1 += __shfl_xor_sync(0xffffffffu, rs1, 2);
    ls0 = ls0 * c0 + rs0;
    ls1 = ls1 * c1 + rs1;
#pragma unroll
    for (int jd = 0; jd < 8; jd++) {
      oacc[jd][0] *= c0; oacc[jd][1] *= c0;
      oacc[jd][2] *= c1; oacc[jd][3] *= c1;
    }

    // ---- O += P V (P from registers; 3-MMA split) ----
#pragma unroll
    for (int ks = 0; ks < 4; ++ks) {
      uint32_t ah[4], al[4];
      split2(sf[2 * ks][0], sf[2 * ks][1], ah[0], al[0]);
      split2(sf[2 * ks][2], sf[2 * ks][3], ah[1], al[1]);
      split2(sf[2 * ks + 1][0], sf[2 * ks + 1][1], ah[2], al[2]);
      split2(sf[2 * ks + 1][2], sf[2 * ks + 1][3], ah[3], al[3]);
#pragma unroll
      for (int jd = 0; jd < 8; jd++) {
        int o = (ks * 8 + t) * 72 + jd * 8 + g;
        uint32_t bh[2] = {Vhp[o], Vhp[o + 4 * 72]};
        uint32_t bl[2] = {Vlp[o], Vlp[o + 4 * 72]};
        mma16816(oacc[jd], ah, bh);
        mma16816(oacc[jd], ah, bl);
        mma16816(oacc[jd], al, bh);
      }
    }
  }

  // ---- epilogue: normalize and store ----
  float inv0 = 1.f / ls0, inv1 = 1.f / ls1;
  float* Op = g_Oh + ((size_t)(b * H_ + h) * S_ + qt * 64 + w * 16) * DK_;
#pragma unroll
  for (int jd = 0; jd < 8; jd++) {
    *(float2*)(Op + (size_t)g * DK_ + jd * 8 + 2 * t) =
        make_float2(oacc[jd][0] * inv0, oacc[jd][1] * inv0);
    *(float2*)(Op + (size_t)(g + 8) * DK_ + jd * 8 + 2 * t) =
        make_float2(oacc[jd][2] * inv1, oacc[jd][3] * inv1);
  }
  (void)r0;
}

// ---------------------------------------------------------------------------
extern "C" void kernel_launch(void* const* d_in, const int* in_sizes, int n_in,
                              void* d_out, int out_size) {
  (void)in_sizes; (void)n_in; (void)out_size;
  const float* dec  = (const float*)d_in[0];
  const float* enc  = (const float*)d_in[1];
  const float* Wq   = (const float*)d_in[2];
  const float* Wkv  = (const float*)d_in[3];
  const float* Wo   = (const float*)d_in[4];
  const int*   mask = (const int*)d_in[5];
  float* out = (float*)d_out;

  float *Qp = nullptr, *KVp = nullptr, *attnp = nullptr;
  cudaGetSymbolAddress((void**)&Qp, g_Q);
  cudaGetSymbolAddress((void**)&KVp, g_KV);
  cudaGetSymbolAddress((void**)&attnp, g_attn);

  cudaFuncSetAttribute(gemm_tc, cudaFuncAttributeMaxDynamicSharedMemorySize, GEMM_SMEM);
  cudaFuncSetAttribute(attn_mma, cudaFuncAttributeMaxDynamicSharedMemorySize, ATTN_SMEM);

  const int M = B_ * S_;  // 4096
  gemm_tc<<<dim3(DIM_ / 128, M / 128), 256, GEMM_SMEM>>>(dec, Wq, Qp, DIM_);
  gemm_tc<<<dim3(2 * DIM_ / 128, M / 128), 256, GEMM_SMEM>>>(enc, Wkv, KVp, 2 * DIM_);
  repack_qkv<<<M, 256>>>();
  attn_mma<<<dim3(S_ / 64, H_, B_), 128, ATTN_SMEM>>>(mask);
  unpack_o<<<M, 256>>>();
  gemm_tc<<<dim3(DIM_ / 128, M / 128), 256, GEMM_SMEM>>>(attnp, Wo, out, DIM_);
}

// round 8
// speedup vs baseline: 2.7727x; 1.1675x over previous
#include <cuda_runtime.h>
#include <cuda_bf16.h>
#include <math_constants.h>
#include <cstdint>

// CrossMHA: B=2, S=2048, DIM=1024, H=16, DK=64, heads-last layout [b,s,dk,h]
namespace {
constexpr int B_ = 2, S_ = 2048, DIM_ = 1024, H_ = 16, DK_ = 64;
constexpr float NEGV = -10000000000.0f;
}

// Scratch (static device globals; no allocation in kernel_launch)
__device__ float g_Q[B_ * S_ * DIM_];        // dec @ Wq^T, [b,s,dim]
__device__ float g_KV[B_ * S_ * 2 * DIM_];   // enc @ Wkv^T, [b,s,2*dim]
__device__ float g_Oh[B_ * S_ * DIM_];       // attention out, [b,h,s,dk]
__device__ float g_attn[B_ * S_ * DIM_];     // repacked to [b,s,dim] heads-last
// Pre-split bf16 packed-pair operands for attention (u32 = 2 bf16)
__device__ uint32_t g_Qph[B_ * H_ * S_ * 32];       // pairs along dk, hi
__device__ uint32_t g_Qpl[B_ * H_ * S_ * 32];       // lo (residual)
__device__ uint32_t g_Kph[B_ * H_ * S_ * 32];
__device__ uint32_t g_Kpl[B_ * H_ * S_ * 32];
__device__ uint32_t g_Vph[B_ * H_ * (S_ / 2) * 64]; // pairs along key
__device__ uint32_t g_Vpl[B_ * H_ * (S_ / 2) * 64];

// ===========================================================================
// Warp-level bf16 MMA helpers (base sm_80+ instructions; assemble on sm_103)
// ===========================================================================
__device__ __forceinline__ uint32_t packbf(__nv_bfloat16 lo, __nv_bfloat16 hi) {
  __nv_bfloat162 t(lo, hi);
  return *reinterpret_cast<uint32_t*>(&t);
}
__device__ __forceinline__ void split2(float x, float y, uint32_t& hi, uint32_t& lo) {
  __nv_bfloat16 bx = __float2bfloat16_rn(x);
  __nv_bfloat16 by = __float2bfloat16_rn(y);
  float rx = x - __bfloat162float(bx);
  float ry = y - __bfloat162float(by);
  hi = packbf(bx, by);
  lo = packbf(__float2bfloat16_rn(rx), __float2bfloat16_rn(ry));
}
__device__ __forceinline__ void mma16816(float* d, const uint32_t* a, const uint32_t* b) {
  asm volatile(
      "mma.sync.aligned.m16n8k16.row.col.f32.bf16.bf16.f32 "
      "{%0,%1,%2,%3}, {%4,%5,%6,%7}, {%8,%9}, {%0,%1,%2,%3};"
      : "+f"(d[0]), "+f"(d[1]), "+f"(d[2]), "+f"(d[3])
      : "r"(a[0]), "r"(a[1]), "r"(a[2]), "r"(a[3]), "r"(b[0]), "r"(b[1]));
}
__device__ __forceinline__ uint32_t smem_u32(const void* p) {
  uint32_t a;
  asm("{ .reg .u64 t; cvta.to.shared.u64 t, %1; cvt.u32.u64 %0, t; }"
      : "=r"(a) : "l"(p));
  return a;
}
__device__ __forceinline__ void cpasync16(uint32_t dst, const void* src) {
  asm volatile("cp.async.ca.shared.global [%0], [%1], 16;" :: "r"(dst), "l"(src));
}
#define CPA_COMMIT() asm volatile("cp.async.commit_group;" ::: "memory")
#define CPA_WAIT(n) asm volatile("cp.async.wait_group %0;" :: "n"(n) : "memory")

// ===========================================================================
// bf16-split GEMM on mma.sync: C[M,N] = A[M,K] * W[N,K]^T  (fp32 in/out)
// Block tile 128x128, 8 warps (2 in M x 4 in N), warp tile 64x32.
// ===========================================================================
namespace {
constexpr int GK = 1024;
constexpr int NCHUNK = GK / 64;
constexpr int R4 = 36;                 // smem row stride in b32 (144 bytes)
constexpr int TILE32 = 128 * R4;
constexpr int GEMM_SMEM = 4 * TILE32 * 4;  // 73728 B
}

__global__ __launch_bounds__(256, 2)
void gemm_tc(const float* __restrict__ A, const float* __restrict__ W,
             float* __restrict__ C, int N) {
  extern __shared__ uint32_t sm[];
  uint32_t* const sAhi = sm;
  uint32_t* const sAlo = sm + TILE32;
  uint32_t* const sWhi = sm + 2 * TILE32;
  uint32_t* const sWlo = sm + 3 * TILE32;

  const int tid = threadIdx.x;
  const int lane = tid & 31;
  const int wid = tid >> 5;
  const int g = lane >> 2;
  const int t = lane & 3;
  const int warp_m = wid & 1;
  const int warp_n = wid >> 1;
  const int bm = blockIdx.y * 128;
  const int bn = blockIdx.x * 128;

  float acc[4][4][4];
#pragma unroll
  for (int mt = 0; mt < 4; mt++)
#pragma unroll
    for (int nt = 0; nt < 4; nt++)
#pragma unroll
      for (int c = 0; c < 4; c++) acc[mt][nt][c] = 0.f;

  const uint32_t* const Awhi = sAhi + (warp_m * 64) * R4;
  const uint32_t* const Awlo = sAlo + (warp_m * 64) * R4;
  const uint32_t* const Bwhi = sWhi + (warp_n * 32) * R4;
  const uint32_t* const Bwlo = sWlo + (warp_n * 32) * R4;

  for (int ch = 0; ch < NCHUNK; ++ch) {
    const int k0 = ch * 64;
    float4 av[8], wv[8];
#pragma unroll
    for (int l = 0; l < 8; ++l) {
      int idx = tid + l * 256;
      int r = idx >> 4;
      int c4 = idx & 15;
      av[l] = *(const float4*)(A + (size_t)(bm + r) * GK + k0 + c4 * 4);
      wv[l] = *(const float4*)(W + (size_t)(bn + r) * GK + k0 + c4 * 4);
    }
    __syncthreads();
#pragma unroll
    for (int l = 0; l < 8; ++l) {
      int idx = tid + l * 256;
      int r = idx >> 4;
      int c4 = idx & 15;
      int base = r * R4 + c4 * 2;
      uint32_t h0, l0, h1, l1;
      split2(av[l].x, av[l].y, h0, l0);
      split2(av[l].z, av[l].w, h1, l1);
      sAhi[base] = h0; sAhi[base + 1] = h1;
      sAlo[base] = l0; sAlo[base + 1] = l1;
      split2(wv[l].x, wv[l].y, h0, l0);
      split2(wv[l].z, wv[l].w, h1, l1);
      sWhi[base] = h0; sWhi[base + 1] = h1;
      sWlo[base] = l0; sWlo[base + 1] = l1;
    }
    __syncthreads();
#pragma unroll
    for (int ks = 0; ks < 4; ++ks) {
      const int kb = ks * 8;
      uint32_t bh[4][2], bl[4][2];
#pragma unroll
      for (int nt = 0; nt < 4; ++nt) {
        int o = (nt * 8 + g) * R4 + kb + t;
        bh[nt][0] = Bwhi[o]; bh[nt][1] = Bwhi[o + 4];
        bl[nt][0] = Bwlo[o]; bl[nt][1] = Bwlo[o + 4];
      }
#pragma unroll
      for (int mt = 0; mt < 4; ++mt) {
        int o0 = (mt * 16 + g) * R4 + kb + t;
        int o1 = o0 + 8 * R4;
        uint32_t ah[4], al[4];
        ah[0] = Awhi[o0]; ah[1] = Awhi[o1]; ah[2] = Awhi[o0 + 4]; ah[3] = Awhi[o1 + 4];
        al[0] = Awlo[o0]; al[1] = Awlo[o1]; al[2] = Awlo[o0 + 4]; al[3] = Awlo[o1 + 4];
#pragma unroll
        for (int nt = 0; nt < 4; ++nt) {
          mma16816(acc[mt][nt], ah, bh[nt]);
          mma16816(acc[mt][nt], ah, bl[nt]);
          mma16816(acc[mt][nt], al, bh[nt]);
        }
      }
    }
  }

#pragma unroll
  for (int mt = 0; mt < 4; ++mt) {
    int row0 = bm + warp_m * 64 + mt * 16 + g;
#pragma unroll
    for (int nt = 0; nt < 4; ++nt) {
      int col = bn + warp_n * 32 + nt * 8 + 2 * t;
      *(float2*)(C + (size_t)row0 * N + col) = make_float2(acc[mt][nt][0], acc[mt][nt][1]);
      *(float2*)(C + (size_t)(row0 + 8) * N + col) = make_float2(acc[mt][nt][2], acc[mt][nt][3]);
    }
  }
}

// ---------------------------------------------------------------------------
// Repack + pre-split: [b,s, d*16+h] fp32 -> packed bf16-pair hi/lo arrays.
// One block per (b, s-pair). Q/K: pairs along dk. V: pairs along key.
// ---------------------------------------------------------------------------
__global__ __launch_bounds__(256)
void repack_qkv() {
  __shared__ float sq[2][1056], sk[2][1056], sv[2][1056];
  const int u = blockIdx.x;            // 0 .. B*S/2-1
  const int b = u >> 10;               // / (S/2)
  const int sp = u & 1023;
  const int s0 = sp * 2;
  const int tid = threadIdx.x;
  const float* q0  = g_Q  + ((size_t)b * S_ + s0) * DIM_;
  const float* kv0 = g_KV + ((size_t)b * S_ + s0) * 2 * DIM_;
#pragma unroll
  for (int l = 0; l < 8; l++) {
    int i = tid + l * 256;             // 0..2047
    int r = i >> 10, c = i & 1023;
    int a = c + (c >> 5);
    sq[r][a] = q0[(size_t)r * DIM_ + c];
    sk[r][a] = kv0[(size_t)r * 2 * DIM_ + c];
    sv[r][a] = kv0[(size_t)r * 2 * DIM_ + DIM_ + c];
  }
  __syncthreads();
  // Q/K: out[(b,h, s0+r)][dd] = pack(x[32dd+h], x[32dd+16+h])
#pragma unroll
  for (int l = 0; l < 4; l++) {
    int idx = tid + l * 256;           // 0..1023
    int r = idx >> 9, rem = idx & 511;
    int h = rem >> 5, dd = rem & 31;
    int a0 = 32 * dd + h;       a0 += a0 >> 5;
    int a1 = 32 * dd + 16 + h;  a1 += a1 >> 5;
    size_t o = ((size_t)(b * H_ + h) * S_ + s0 + r) * 32 + dd;
    uint32_t hi, lo;
    split2(sq[r][a0], sq[r][a1], hi, lo);
    g_Qph[o] = hi; g_Qpl[o] = lo;
    split2(sk[r][a0], sk[r][a1], hi, lo);
    g_Kph[o] = hi; g_Kpl[o] = lo;
  }
  // V: out[(b,h, sp)][d] = pack(V[s0][d], V[s0+1][d])
#pragma unroll
  for (int l = 0; l < 4; l++) {
    int idx = tid + l * 256;           // 0..1023
    int h = idx >> 6, d = idx & 63;
    int a = d * 16 + h; a += a >> 5;
    uint32_t hi, lo;
    split2(sv[0][a], sv[1][a], hi, lo);
    size_t o = ((size_t)(b * H_ + h) * (S_ / 2) + sp) * 64 + d;
    g_Vph[o] = hi; g_Vpl[o] = lo;
  }
}

// ---------------------------------------------------------------------------
// Unpack: [b,h,s,d] -> [b,s, d*16+h]
// ---------------------------------------------------------------------------
__global__ void unpack_o() {
  __shared__ float buf[1056];
  const int bs = blockIdx.x;
  const int b = bs >> 11;
  const int s = bs & (S_ - 1);
  const int tid = threadIdx.x;
#pragma unroll
  for (int l = 0; l < 4; l++) {
    int idx = tid + l * 256;
    int h = idx >> 6, d = idx & 63;
    int a = d * H_ + h;
    buf[a + (a >> 5)] = g_Oh[((size_t)(b * H_ + h) * S_ + s) * DK_ + d];
  }
  __syncthreads();
#pragma unroll
  for (int l = 0; l < 4; l++) {
    int i = tid + l * 256;
    g_attn[(size_t)bs * DIM_ + i] = buf[i + (i >> 5)];
  }
}

// ===========================================================================
// Tensor-core flash attention, cp.async double-buffered.
// Block = 256 threads (8 warps), 128 q rows; warp w: rows [16w,16w+16).
// Key tiles of 64. Operands pre-split bf16 pairs in gmem.
// SMEM (u32 idx): Q hi[0,4608) lo[4608,9216); K stages at 9216+st*4608
// (hi 2304, lo 2304); V stages at 18432+st*4608. Total 27648 u32 = 110592 B.
// ===========================================================================
namespace {
constexpr int AQ = 0;
constexpr int AK = 9216;
constexpr int AV = 18432;
constexpr int ATTN_SMEM = 27648 * 4;   // 110592 B
}

__global__ __launch_bounds__(256, 2)
void attn_mma(const int* __restrict__ mask) {
  extern __shared__ uint32_t smem[];
  const uint32_t sb = smem_u32(smem);
  const int qt = blockIdx.x, h = blockIdx.y, b = blockIdx.z;
  const int tid = threadIdx.x;
  const int lane = tid & 31, w = tid >> 5;
  const int g = lane >> 2, t = lane & 3;
  const int bh = b * H_ + h;
  const uint32_t* const Qsh = g_Qph + ((size_t)bh * S_ + qt * 128) * 32;
  const uint32_t* const Qsl = g_Qpl + ((size_t)bh * S_ + qt * 128) * 32;
  const uint32_t* const Ksh = g_Kph + (size_t)bh * S_ * 32;
  const uint32_t* const Ksl = g_Kpl + (size_t)bh * S_ * 32;
  const uint32_t* const Vsh = g_Vph + (size_t)bh * (S_ / 2) * 64;
  const uint32_t* const Vsl = g_Vpl + (size_t)bh * (S_ / 2) * 64;
  const int* const Mp = mask + ((size_t)b * S_ + qt * 128) * S_;

  // ---- prologue: Q tile + key-tile 0 into stage 0, one cp.async group ----
#pragma unroll
  for (int l = 0; l < 4; l++) {
    int idx = tid + l * 256;        // 0..1023
    int r = idx >> 3, c = (idx & 7) * 4;
    cpasync16(sb + (AQ + r * R4 + c) * 4, Qsh + r * 32 + c);
    cpasync16(sb + (AQ + 4608 + r * R4 + c) * 4, Qsl + r * 32 + c);
  }
  {
#pragma unroll
    for (int l = 0; l < 2; l++) {
      int idx = tid + l * 256;      // 0..511
      int r = idx >> 3, c = (idx & 7) * 4;
      uint32_t d = sb + (AK + r * R4 + c) * 4;
      cpasync16(d, Ksh + r * 32 + c);
      cpasync16(d + 2304 * 4, Ksl + r * 32 + c);
      int rv = idx >> 4, cv = (idx & 15) * 4;
      uint32_t dv = sb + (AV + rv * 72 + cv) * 4;
      cpasync16(dv, Vsh + rv * 64 + cv);
      cpasync16(dv + 2304 * 4, Vsl + rv * 64 + cv);
    }
  }
  CPA_COMMIT();

  float m0 = -CUDART_INF_F, m1 = -CUDART_INF_F, ls0 = 0.f, ls1 = 0.f;
  float oacc[8][4];
#pragma unroll
  for (int jd = 0; jd < 8; jd++)
#pragma unroll
    for (int c = 0; c < 4; c++) oacc[jd][c] = 0.f;

  const uint32_t* const Qbh = smem + AQ + (w * 16) * R4;
  const uint32_t* const Qbl = Qbh + 4608;

  for (int it = 0; it < S_ / 64; ++it) {
    // issue next tile into the other stage, then wait for current
    if (it + 1 < S_ / 64) {
      const int kn = (it + 1) * 64;
      const int st = (it + 1) & 1;
#pragma unroll
      for (int l = 0; l < 2; l++) {
        int idx = tid + l * 256;
        int r = idx >> 3, c = (idx & 7) * 4;
        uint32_t d = sb + (AK + st * 4608 + r * R4 + c) * 4;
        cpasync16(d, Ksh + (size_t)(kn + r) * 32 + c);
        cpasync16(d + 2304 * 4, Ksl + (size_t)(kn + r) * 32 + c);
        int rv = idx >> 4, cv = (idx & 15) * 4;
        uint32_t dv = sb + (AV + st * 4608 + rv * 72 + cv) * 4;
        cpasync16(dv, Vsh + (size_t)(kn / 2 + rv) * 64 + cv);
        cpasync16(dv + 2304 * 4, Vsl + (size_t)(kn / 2 + rv) * 64 + cv);
      }
      CPA_COMMIT();
      CPA_WAIT(1);
    } else {
      CPA_WAIT(0);
    }
    __syncthreads();

    const uint32_t* const Khi = smem + AK + (it & 1) * 4608;
    const uint32_t* const Klo = Khi + 2304;
    const uint32_t* const Vhp = smem + AV + (it & 1) * 4608;
    const uint32_t* const Vlp = Vhp + 2304;
    const int k0 = it * 64;

    // ---- S = Q K^T (3-MMA split) ----
    float sf[8][4];
#pragma unroll
    for (int j = 0; j < 8; j++)
#pragma unroll
      for (int c = 0; c < 4; c++) sf[j][c] = 0.f;

#pragma unroll
    for (int ks = 0; ks < 4; ++ks) {
      const int kb = ks * 8;
      uint32_t ah[4], al[4];
      ah[0] = Qbh[g * R4 + kb + t];       ah[1] = Qbh[(g + 8) * R4 + kb + t];
      ah[2] = Qbh[g * R4 + kb + t + 4];   ah[3] = Qbh[(g + 8) * R4 + kb + t + 4];
      al[0] = Qbl[g * R4 + kb + t];       al[1] = Qbl[(g + 8) * R4 + kb + t];
      al[2] = Qbl[g * R4 + kb + t + 4];   al[3] = Qbl[(g + 8) * R4 + kb + t + 4];
#pragma unroll
      for (int j = 0; j < 8; j++) {
        int o = (j * 8 + g) * R4 + kb + t;
        uint32_t bh2[2] = {Khi[o], Khi[o + 4]};
        uint32_t bl2[2] = {Klo[o], Klo[o + 4]};
        mma16816(sf[j], ah, bh2);
        mma16816(sf[j], ah, bl2);
        mma16816(sf[j], al, bh2);
      }
    }

    // ---- scale + mask ----
#pragma unroll
    for (int j = 0; j < 8; j++) {
      int col = k0 + j * 8 + 2 * t;
      int2 ma = *(const int2*)(Mp + (size_t)(w * 16 + g) * S_ + col);
      int2 mb = *(const int2*)(Mp + (size_t)(w * 16 + g + 8) * S_ + col);
      sf[j][0] = ma.x ? sf[j][0] * 0.125f : NEGV;
      sf[j][1] = ma.y ? sf[j][1] * 0.125f : NEGV;
      sf[j][2] = mb.x ? sf[j][2] * 0.125f : NEGV;
      sf[j][3] = mb.y ? sf[j][3] * 0.125f : NEGV;
    }

    // ---- online softmax (rows g, g+8; reduce across 4 t-lanes) ----
    float rm0 = -CUDART_INF_F, rm1 = -CUDART_INF_F;
#pragma unroll
    for (int j = 0; j < 8; j++) {
      rm0 = fmaxf(rm0, fmaxf(sf[j][0], sf[j][1]));
      rm1 = fmaxf(rm1, fmaxf(sf[j][2], sf[j][3]));
    }
    rm0 = fmaxf(rm0, __shfl_xor_sync(0xffffffffu, rm0, 1));
    rm0 = fmaxf(rm0, __shfl_xor_sync(0xffffffffu, rm0, 2));
    rm1 = fmaxf(rm1, __shfl_xor_sync(0xffffffffu, rm1, 1));
    rm1 = fmaxf(rm1, __shfl_xor_sync(0xffffffffu, rm1, 2));
    float mn0 = fmaxf(m0, rm0), mn1 = fmaxf(m1, rm1);
    float c0 = __expf(m0 - mn0), c1 = __expf(m1 - mn1);
    m0 = mn0; m1 = mn1;
    float rs0 = 0.f, rs1 = 0.f;
#pragma unroll
    for (int j = 0; j < 8; j++) {
      sf[j][0] = __expf(sf[j][0] - mn0);
      sf[j][1] = __expf(sf[j][1] - mn0);
      sf[j][2] = __expf(sf[j][2] - mn1);
      sf[j][3] = __expf(sf[j][3] - mn1);
      rs0 += sf[j][0] + sf[j][1];
      rs1 += sf[j][2] + sf[j][3];
    }
    rs0 += __shfl_xor_sync(0xffffffffu, rs0, 1);
    rs0 += __shfl_xor_sync(0xffffffffu, rs0, 2);
    rs1 += __shfl_xor_sync(0xffffffffu, rs1, 1);
    rs1 += __shfl_xor_sync(0xffffffffu, rs1, 2);
    ls0 = ls0 * c0 + rs0;
    ls1 = ls1 * c1 + rs1;
#pragma unroll
    for (int jd = 0; jd < 8; jd++) {
      oacc[jd][0] *= c0; oacc[jd][1] *= c0;
      oacc[jd][2] *= c1; oacc[jd][3] *= c1;
    }

    // ---- O += P V (3-MMA split; P from registers) ----
#pragma unroll
    for (int ks = 0; ks < 4; ++ks) {
      uint32_t ah[4], al[4];
      split2(sf[2 * ks][0], sf[2 * ks][1], ah[0], al[0]);
      split2(sf[2 * ks][2], sf[2 * ks][3], ah[1], al[1]);
      split2(sf[2 * ks + 1][0], sf[2 * ks + 1][1], ah[2], al[2]);
      split2(sf[2 * ks + 1][2], sf[2 * ks + 1][3], ah[3], al[3]);
#pragma unroll
      for (int jd = 0; jd < 8; jd++) {
        int o = (ks * 8 + t) * 72 + jd * 8 + g;
        uint32_t bh2[2] = {Vhp[o], Vhp[o + 4 * 72]};
        uint32_t bl2[2] = {Vlp[o], Vlp[o + 4 * 72]};
        mma16816(oacc[jd], ah, bh2);
        mma16816(oacc[jd], ah, bl2);
        mma16816(oacc[jd], al, bh2);
      }
    }
    __syncthreads();   // stage (it&1) fully consumed before iter it+1 overwrites... (it+2 uses it; safe gap)
  }

  // ---- epilogue: normalize and store ----
  float inv0 = 1.f / ls0, inv1 = 1.f / ls1;
  float* Op = g_Oh + ((size_t)bh * S_ + qt * 128 + w * 16) * DK_;
#pragma unroll
  for (int jd = 0; jd < 8; jd++) {
    *(float2*)(Op + (size_t)g * DK_ + jd * 8 + 2 * t) =
        make_float2(oacc[jd][0] * inv0, oacc[jd][1] * inv0);
    *(float2*)(Op + (size_t)(g + 8) * DK_ + jd * 8 + 2 * t) =
        make_float2(oacc[jd][2] * inv1, oacc[jd][3] * inv1);
  }
}

// ---------------------------------------------------------------------------
extern "C" void kernel_launch(void* const* d_in, const int* in_sizes, int n_in,
                              void* d_out, int out_size) {
  (void)in_sizes; (void)n_in; (void)out_size;
  const float* dec  = (const float*)d_in[0];
  const float* enc  = (const float*)d_in[1];
  const float* Wq   = (const float*)d_in[2];
  const float* Wkv  = (const float*)d_in[3];
  const float* Wo   = (const float*)d_in[4];
  const int*   mask = (const int*)d_in[5];
  float* out = (float*)d_out;

  float *Qp = nullptr, *KVp = nullptr, *attnp = nullptr;
  cudaGetSymbolAddress((void**)&Qp, g_Q);
  cudaGetSymbolAddress((void**)&KVp, g_KV);
  cudaGetSymbolAddress((void**)&attnp, g_attn);

  cudaFuncSetAttribute(gemm_tc, cudaFuncAttributeMaxDynamicSharedMemorySize, GEMM_SMEM);
  cudaFuncSetAttribute(attn_mma, cudaFuncAttributeMaxDynamicSharedMemorySize, ATTN_SMEM);

  const int M = B_ * S_;  // 4096
  gemm_tc<<<dim3(DIM_ / 128, M / 128), 256, GEMM_SMEM>>>(dec, Wq, Qp, DIM_);
  gemm_tc<<<dim3(2 * DIM_ / 128, M / 128), 256, GEMM_SMEM>>>(enc, Wkv, KVp, 2 * DIM_);
  repack_qkv<<<M / 2, 256>>>();
  attn_mma<<<dim3(S_ / 128, H_, B_), 256, ATTN_SMEM>>>(mask);
  unpack_o<<<M, 256>>>();
  gemm_tc<<<dim3(DIM_ / 128, M / 128), 256, GEMM_SMEM>>>(attnp, Wo, out, DIM_);
}